// round 5
// baseline (speedup 1.0000x reference)
#include <cuda_runtime.h>
#include <cstdint>

// Problem constants
#define BATCH   32768
#define TSTEPS  30
#define HID     384
#define KTOT    392     // 8 rowvec + 384 hidden
#define NKB     49      // K blocks of 8
#define NMAIN   144     // n8 fragments per kb in main B (24 ub * 6)
#define MROWS   64      // batch rows per CTA
#define NTH     512     // 16 warps: 2 M-halves x 8 warps
#define LDH     392     // sA row stride in floats (392 % 32 == 8 -> conflict-free)
#define LDH2    196     // row stride in float2
#define ASZ     (MROWS*LDH)

// -------- static device scratch --------
__device__ float2 g_B2[NKB * NMAIN * 32];   // main GEMM B (r,z,n_h), fragment order
__device__ float2 g_Bni[48 * 32];           // n_i B: kb=0 only, 24 ub * 2 uh
__device__ float2 g_Wd1f2[48 * 8 * 32];     // decode B, fragment order

__device__ __forceinline__ float to_tf32(float x) {
    unsigned u; asm("cvt.rna.tf32.f32 %0, %1;" : "=r"(u) : "f"(x));
    return __uint_as_float(u);
}
__device__ __forceinline__ float sigf(float x) { return 1.0f / (1.0f + __expf(-x)); }
__device__ __forceinline__ float tanhf_fast(float x) {
    return 2.0f / (1.0f + __expf(-2.0f * x)) - 1.0f;
}

__device__ __forceinline__ void mma_tf32(float* c, const unsigned* a, unsigned b0, unsigned b1) {
    asm volatile(
        "mma.sync.aligned.m16n8k8.row.col.f32.tf32.tf32.f32 "
        "{%0,%1,%2,%3}, {%4,%5,%6,%7}, {%8,%9}, {%0,%1,%2,%3};\n"
        : "+f"(c[0]), "+f"(c[1]), "+f"(c[2]), "+f"(c[3])
        : "r"(a[0]), "r"(a[1]), "r"(a[2]), "r"(a[3]), "r"(b0), "r"(b1));
}

// packed A element index: float offset of logical A[r][c]
// layout: per 8-col block kb, float2 pairs {A[8kb+t], A[8kb+t+4]} for t in [0,4)
__device__ __forceinline__ int aidx(int r, int c) {
    return r * LDH + (c & ~7) + ((c & 3) << 1) + ((c >> 2) & 1);
}

// load one mf's A fragment (rows rbase, rbase+8; cols tig, tig+4 of block kb)
__device__ __forceinline__ void load_a_pair(unsigned* dst, const float2* Af2,
                                            int rbase, int kb4tig) {
    float2 lo = Af2[rbase * LDH2 + kb4tig];
    float2 hi = Af2[(rbase + 8) * LDH2 + kb4tig];
    dst[0] = __float_as_uint(lo.x);
    dst[1] = __float_as_uint(hi.x);
    dst[2] = __float_as_uint(lo.y);
    dst[3] = __float_as_uint(hi.y);
}

// -------- prep helpers (layouts unchanged from round 4) --------
__device__ float bval_main(int k, int ub, int colub,
                           const float* Wih, const float* bih,
                           const float* Whh, const float* bhh,
                           const float* Wp, const float* bp,
                           const float* Ws, const float* bs) {
    int gate = colub >> 4;          // 0=r,1=z,2=n_h
    int u = ub * 16 + (colub & 15);
    if (k >= 8) {
        int kk = k - 8;
        int grow = (gate == 2 ? 768 : gate * 384) + u;
        return Whh[grow * HID + kk];
    }
    if (gate == 2) return (k == 0) ? bhh[768 + u] : 0.0f;   // n_h: bias only
    int grow = gate * 384 + u;
    const float* wr = Wih + grow * 128;
    float s = 0.0f;
    if (k == 0) {
        s = bih[grow] + bhh[grow];
        for (int m = 0; m < 128; m++) s += bs[m] * wr[m];
    } else if (k == 1) {
        for (int m = 0; m < 128; m++) s += bp[m] * wr[m];
    } else if (k < 5) {
        int d = k - 2;
        for (int m = 0; m < 128; m++) s += Ws[m * 3 + d] * wr[m];
    } else {
        int d = k - 5;
        for (int m = 0; m < 128; m++) s += Wp[m * 3 + d] * wr[m];
    }
    return s;
}

__device__ float bval_ni(int k, int u,
                         const float* Wih, const float* bih,
                         const float* Wp, const float* bp,
                         const float* Ws, const float* bs) {
    int grow = 768 + u;
    const float* wr = Wih + grow * 128;
    float s = 0.0f;
    if (k == 0) {
        s = bih[grow];
        for (int m = 0; m < 128; m++) s += bs[m] * wr[m];
    } else if (k == 1) {
        for (int m = 0; m < 128; m++) s += bp[m] * wr[m];
    } else if (k < 5) {
        int d = k - 2;
        for (int m = 0; m < 128; m++) s += Ws[m * 3 + d] * wr[m];
    } else {
        int d = k - 5;
        for (int m = 0; m < 128; m++) s += Wp[m * 3 + d] * wr[m];
    }
    return s;
}

__global__ void prep_kernel(const float* __restrict__ W_ih, const float* __restrict__ b_ih,
                            const float* __restrict__ W_hh, const float* __restrict__ b_hh,
                            const float* __restrict__ Wp,  const float* __restrict__ bp,
                            const float* __restrict__ Ws,  const float* __restrict__ bs,
                            const float* __restrict__ Wd1) {
    int gid = blockIdx.x * blockDim.x + threadIdx.x;
    int nMain = NKB * NMAIN;
    int total = (nMain + 48 + 48 * 8) * 32;
    for (int w = gid; w < total; w += gridDim.x * blockDim.x) {
        int fid = w >> 5, lane = w & 31;
        int tig = lane & 3, g = lane >> 2;
        if (fid < nMain) {
            int kb = fid / NMAIN, rem = fid - kb * NMAIN;
            int ub = rem / 6, n8l = rem - ub * 6;
            int colub = n8l * 8 + g;
            float b0 = bval_main(kb * 8 + tig,     ub, colub, W_ih, b_ih, W_hh, b_hh, Wp, bp, Ws, bs);
            float b1 = bval_main(kb * 8 + tig + 4, ub, colub, W_ih, b_ih, W_hh, b_hh, Wp, bp, Ws, bs);
            g_B2[fid * 32 + lane] = make_float2(to_tf32(b0), to_tf32(b1));
        } else if (fid < nMain + 48) {
            int f = fid - nMain;            // ub*2 + uh
            int ub = f >> 1, n8l = f & 1;
            int u = ub * 16 + n8l * 8 + g;
            float b0 = bval_ni(tig,     u, W_ih, b_ih, Wp, bp, Ws, bs);
            float b1 = bval_ni(tig + 4, u, W_ih, b_ih, Wp, bp, Ws, bs);
            g_Bni[f * 32 + lane] = make_float2(to_tf32(b0), to_tf32(b1));
        } else {
            int f = fid - nMain - 48;       // 48 kb * 8 n8
            int kb = f >> 3, n8 = f & 7;
            int n = n8 * 8 + g;
            int k = kb * 8 + tig;
            float b0 = Wd1[n * HID + k];
            float b1 = Wd1[n * HID + k + 4];
            g_Wd1f2[f * 32 + lane] = make_float2(to_tf32(b0), to_tf32(b1));
        }
    }
}

// -------- main fused GRU rollout --------
__global__ __launch_bounds__(NTH, 1)
void gru_kernel(const float* __restrict__ init_hidden,
                const float* __restrict__ plan,
                const float* __restrict__ gate,
                const float* __restrict__ init_state,
                const float* __restrict__ bd1,
                const float* __restrict__ Wd2,
                const float* __restrict__ bd2,
                float* __restrict__ out) {
    extern __shared__ float sm[];
    float* sA0  = sm;                  // [MROWS][LDH] packed, ping
    float* sA1  = sA0 + ASZ;           // pong
    float* sDec = sA1 + ASZ;           // [64][68]
    float* sbd1 = sDec + 64 * 68;      // [64]
    float* sWd2 = sbd1 + 64;           // [3*64]
    float* sbd2 = sWd2 + 192;          // [4]

    const int tid  = threadIdx.x;
    const int warp = tid >> 5;
    const int lane = tid & 31;
    const int g8   = lane >> 2;
    const int tig  = lane & 3;
    const int wsub = warp & 7;          // column-warp within half
    const int mh   = warp >> 3;         // M half (rows mh*32..mh*32+31)
    const int row0 = blockIdx.x * MROWS;

    // per-thread decode/state lane (valid for tid < 192)
    const int pr = tid / 3;
    const int pc = tid - pr * 3;
    float st = 0.0f, gx = 0.0f;

    // ---- init ----
    for (int i = tid; i < MROWS * HID; i += NTH) {
        int r = i / HID, u = i - r * HID;
        sA0[aidx(r, 8 + u)] = to_tf32(init_hidden[(size_t)row0 * HID + i]);
    }
    if (tid < 192) {
        st = init_state[(size_t)row0 * 3 + tid];
        gx = gate[row0 + pr];
        sA0[aidx(pr, 2 + pc)] = to_tf32(st);
        float p0 = plan[((size_t)(row0 + pr) * TSTEPS + 0) * 3 + pc];
        sA0[aidx(pr, 5 + pc)] = to_tf32(gx * p0);
        if (pc == 0) {
            sA0[aidx(pr, 0)] = 1.0f;          sA1[aidx(pr, 0)] = 1.0f;
            sA0[aidx(pr, 1)] = to_tf32(gx);   sA1[aidx(pr, 1)] = to_tf32(gx);
        }
        sWd2[tid] = Wd2[tid];
    }
    if (tid < 64) sbd1[tid] = bd1[tid];
    if (tid < 3)  sbd2[tid] = bd2[tid];
    __syncthreads();

    for (int t = 0; t < TSTEPS; t++) {
        float* Acur = (t & 1) ? sA1 : sA0;
        float* Anxt = (t & 1) ? sA0 : sA1;
        const float2* Af2  = (const float2*)Acur;
        const float2* An2  = (const float2*)Anxt;

        // prefetch plan(t+1) (hidden behind the GEMM)
        float pl = 0.0f;
        if (t < TSTEPS - 1 && tid < 192)
            pl = plan[((size_t)(row0 + pr) * TSTEPS + t + 1) * 3 + pc];

        // ---- phase 1: GEMM (M-half x 1152 dense + n_i micro) + gate math ----
        for (int task = 0; task < 3; task++) {
            const int ub = wsub + 8 * task;     // u-block 0..23

            float acc[48];                      // [mf][6 frags] x 4 (r,z,n_h)
            float accN[16];                     // [mf][uh] x 4 (n_i)
            #pragma unroll
            for (int i = 0; i < 48; i++) acc[i] = 0.0f;
            #pragma unroll
            for (int i = 0; i < 16; i++) accN[i] = 0.0f;

            const float2* Bbase = g_B2 + (size_t)(ub * 6) * 32 + lane;
            float2 bb[2][6];
            #pragma unroll
            for (int j = 0; j < 6; j++) bb[0][j] = Bbase[j * 32];
            float2 bni0 = g_Bni[(ub * 2 + 0) * 32 + lane];
            float2 bni1 = g_Bni[(ub * 2 + 1) * 32 + lane];

            unsigned a[2][8];
            load_a_pair(a[0] + 0, Af2, mh * 32 + g8,      tig);
            load_a_pair(a[0] + 4, Af2, mh * 32 + 16 + g8, tig);

            #pragma unroll 2
            for (int kb = 0; kb < NKB; kb++) {
                const int cur = kb & 1;
                if (kb < NKB - 1) {
                    const float2* Bn = Bbase + (size_t)(kb + 1) * (NMAIN * 32);
                    #pragma unroll
                    for (int j = 0; j < 6; j++) bb[cur ^ 1][j] = Bn[j * 32];
                    load_a_pair(a[cur ^ 1] + 0, Af2, mh * 32 + g8,      (kb + 1) * 4 + tig);
                    load_a_pair(a[cur ^ 1] + 4, Af2, mh * 32 + 16 + g8, (kb + 1) * 4 + tig);
                }
                if (kb == 0) {   // n_i: rowvec-only contribution
                    unsigned n0x = __float_as_uint(bni0.x), n0y = __float_as_uint(bni0.y);
                    unsigned n1x = __float_as_uint(bni1.x), n1y = __float_as_uint(bni1.y);
                    #pragma unroll
                    for (int mf = 0; mf < 2; mf++) {
                        mma_tf32(&accN[(mf * 2 + 0) * 4], &a[cur][mf * 4], n0x, n0y);
                        mma_tf32(&accN[(mf * 2 + 1) * 4], &a[cur][mf * 4], n1x, n1y);
                    }
                }
                #pragma unroll
                for (int f = 0; f < 6; f++) {
                    unsigned b0 = __float_as_uint(bb[cur][f].x);
                    unsigned b1 = __float_as_uint(bb[cur][f].y);
                    #pragma unroll
                    for (int mf = 0; mf < 2; mf++)
                        mma_tf32(&acc[(mf * 6 + f) * 4], &a[cur][mf * 4], b0, b1);
                }
            }

            // gate math on fragments (f = gate*2 + uh)
            #pragma unroll
            for (int mf = 0; mf < 2; mf++)
            #pragma unroll
            for (int uh = 0; uh < 2; uh++)
            #pragma unroll
            for (int e = 0; e < 4; e++) {
                int row = mh * 32 + mf * 16 + g8 + ((e >> 1) << 3);
                int u   = ub * 16 + uh * 8 + tig * 2 + (e & 1);
                float aR  = acc[(mf * 6 + 0 + uh) * 4 + e];
                float aZ  = acc[(mf * 6 + 2 + uh) * 4 + e];
                float aNh = acc[(mf * 6 + 4 + uh) * 4 + e];
                float aNi = accN[(mf * 2 + uh) * 4 + e];
                float rg = sigf(aR);
                float zg = sigf(aZ);
                float n  = tanhf_fast(aNi + rg * aNh);
                float hold = Acur[aidx(row, 8 + u)];
                float hnew = (1.0f - zg) * n + zg * hold;
                Anxt[aidx(row, 8 + u)] = to_tf32(hnew);
            }
        }
        // per-half barrier: phase 2 only reads this half's Anxt rows
        asm volatile("bar.sync %0, %1;" :: "r"(1 + mh), "r"(256) : "memory");

        // ---- phase 2: decode layer1 (64x64, K=384), per M-half ----
        {
            float dacc[8];
            #pragma unroll
            for (int i = 0; i < 8; i++) dacc[i] = 0.0f;

            float2 bv = g_Wd1f2[wsub * 32 + lane];
            unsigned a[2][8];
            load_a_pair(a[0] + 0, An2, mh * 32 + g8,      4 + tig);   // kd=0 -> kb 1
            load_a_pair(a[0] + 4, An2, mh * 32 + 16 + g8, 4 + tig);

            #pragma unroll 2
            for (int kd = 0; kd < 48; kd++) {
                const int cur = kd & 1;
                float2 bcur = bv;
                if (kd < 47) {
                    bv = g_Wd1f2[((kd + 1) * 8 + wsub) * 32 + lane];
                    load_a_pair(a[cur ^ 1] + 0, An2, mh * 32 + g8,      (kd + 2) * 4 + tig);
                    load_a_pair(a[cur ^ 1] + 4, An2, mh * 32 + 16 + g8, (kd + 2) * 4 + tig);
                }
                unsigned b0 = __float_as_uint(bcur.x), b1 = __float_as_uint(bcur.y);
                #pragma unroll
                for (int mf = 0; mf < 2; mf++)
                    mma_tf32(&dacc[mf * 4], &a[cur][mf * 4], b0, b1);
            }
            #pragma unroll
            for (int mf = 0; mf < 2; mf++)
            #pragma unroll
            for (int e = 0; e < 4; e++) {
                int row = mh * 32 + mf * 16 + g8 + ((e >> 1) << 3);
                int col = wsub * 8 + tig * 2 + (e & 1);
                float v = dacc[mf * 4 + e] + sbd1[col];
                v = v > 0.0f ? v : (__expf(v) - 1.0f);   // ELU
                sDec[row * 68 + col] = v;
            }
        }
        __syncthreads();

        // ---- phase 3: decode layer2 + state update + output + next rowvec ----
        if (tid < 192) {
            float acc = sbd2[pc];
            const float* w2 = sWd2 + pc * 64;
            const float* dp = sDec + pr * 68;
            #pragma unroll 16
            for (int k = 0; k < 64; k++) acc += dp[k] * w2[k];
            st += acc;
            out[((size_t)(row0 + pr) * TSTEPS + t) * 3 + pc] = st;
            if (t < TSTEPS - 1) {
                Anxt[aidx(pr, 2 + pc)] = to_tf32(st);
                Anxt[aidx(pr, 5 + pc)] = to_tf32(gx * pl);
            }
        }
        __syncthreads();
    }
}

// -------- launch --------
extern "C" void kernel_launch(void* const* d_in, const int* in_sizes, int n_in,
                              void* d_out, int out_size) {
    const float* init_hidden = (const float*)d_in[0];
    const float* plan        = (const float*)d_in[1];
    const float* gatep       = (const float*)d_in[2];
    const float* init_state  = (const float*)d_in[3];
    const float* Wp   = (const float*)d_in[4];
    const float* bp   = (const float*)d_in[5];
    const float* Ws   = (const float*)d_in[6];
    const float* bs   = (const float*)d_in[7];
    const float* W_ih = (const float*)d_in[8];
    const float* b_ih = (const float*)d_in[9];
    const float* W_hh = (const float*)d_in[10];
    const float* b_hh = (const float*)d_in[11];
    const float* Wd1  = (const float*)d_in[12];
    const float* bd1  = (const float*)d_in[13];
    const float* Wd2  = (const float*)d_in[14];
    const float* bd2  = (const float*)d_in[15];
    float* out = (float*)d_out;

    prep_kernel<<<640, 256>>>(W_ih, b_ih, W_hh, b_hh, Wp, bp, Ws, bs, Wd1);

    const size_t smem_floats = 2 * (size_t)ASZ + 64 * 68 + 64 + 192 + 4;
    const size_t smem_bytes = smem_floats * sizeof(float);
    cudaFuncSetAttribute(gru_kernel, cudaFuncAttributeMaxDynamicSharedMemorySize,
                         (int)smem_bytes);

    gru_kernel<<<BATCH / MROWS, NTH, smem_bytes>>>(
        init_hidden, plan, gatep, init_state, bd1, Wd2, bd2, out);
}

// round 6
// speedup vs baseline: 1.1942x; 1.1942x over previous
#include <cuda_runtime.h>
#include <cstdint>

// Problem constants
#define BATCH   32768
#define TSTEPS  30
#define HID     384
#define KTOT    392     // 8 rowvec + 384 hidden
#define NKB     49      // K blocks of 8
#define NMAIN   144     // n8 fragments per kb in main B (24 ub * 6)
#define MROWS   64      // batch rows per CTA
#define NTH     512     // 16 warps: 2 M-halves x 8 column-warps
#define LDH     396     // sA row stride (392 + 4)
#define ASZ     (MROWS*LDH)

// -------- static device scratch --------
__device__ float2 g_B2[NKB * NMAIN * 32];   // main GEMM B (r,z,n_h), fragment order
__device__ float2 g_Bni[48 * 32];           // n_i B: kb=0 only, 24 ub * 2 uh
__device__ float2 g_Wd1f2[48 * 8 * 32];     // decode B, fragment order

__device__ __forceinline__ float to_tf32(float x) {
    unsigned u; asm("cvt.rna.tf32.f32 %0, %1;" : "=r"(u) : "f"(x));
    return __uint_as_float(u);
}
__device__ __forceinline__ float sigf(float x) { return 1.0f / (1.0f + __expf(-x)); }
__device__ __forceinline__ float tanhf_fast(float x) {
    return 2.0f / (1.0f + __expf(-2.0f * x)) - 1.0f;
}

__device__ __forceinline__ void mma_tf32(float* c, const unsigned* a, unsigned b0, unsigned b1) {
    asm volatile(
        "mma.sync.aligned.m16n8k8.row.col.f32.tf32.tf32.f32 "
        "{%0,%1,%2,%3}, {%4,%5,%6,%7}, {%8,%9}, {%0,%1,%2,%3};\n"
        : "+f"(c[0]), "+f"(c[1]), "+f"(c[2]), "+f"(c[3])
        : "f"(__uint_as_float(a[0])) , "r"(a[1]), "r"(a[2]), "r"(a[3]), "r"(b0), "r"(b1));
}

// NOTE: fixed operand constraint below (all "r")
__device__ __forceinline__ void mma_tf32r(float* c, const unsigned* a, unsigned b0, unsigned b1) {
    asm volatile(
        "mma.sync.aligned.m16n8k8.row.col.f32.tf32.tf32.f32 "
        "{%0,%1,%2,%3}, {%4,%5,%6,%7}, {%8,%9}, {%0,%1,%2,%3};\n"
        : "+f"(c[0]), "+f"(c[1]), "+f"(c[2]), "+f"(c[3])
        : "r"(a[0]), "r"(a[1]), "r"(a[2]), "r"(a[3]), "r"(b0), "r"(b1));
}

// -------- prep helpers (layouts unchanged) --------
__device__ float bval_main(int k, int ub, int colub,
                           const float* Wih, const float* bih,
                           const float* Whh, const float* bhh,
                           const float* Wp, const float* bp,
                           const float* Ws, const float* bs) {
    int gate = colub >> 4;          // 0=r,1=z,2=n_h
    int u = ub * 16 + (colub & 15);
    if (k >= 8) {
        int kk = k - 8;
        int grow = (gate == 2 ? 768 : gate * 384) + u;
        return Whh[grow * HID + kk];
    }
    if (gate == 2) return (k == 0) ? bhh[768 + u] : 0.0f;   // n_h: bias only
    int grow = gate * 384 + u;
    const float* wr = Wih + grow * 128;
    float s = 0.0f;
    if (k == 0) {
        s = bih[grow] + bhh[grow];
        for (int m = 0; m < 128; m++) s += bs[m] * wr[m];
    } else if (k == 1) {
        for (int m = 0; m < 128; m++) s += bp[m] * wr[m];
    } else if (k < 5) {
        int d = k - 2;
        for (int m = 0; m < 128; m++) s += Ws[m * 3 + d] * wr[m];
    } else {
        int d = k - 5;
        for (int m = 0; m < 128; m++) s += Wp[m * 3 + d] * wr[m];
    }
    return s;
}

__device__ float bval_ni(int k, int u,
                         const float* Wih, const float* bih,
                         const float* Wp, const float* bp,
                         const float* Ws, const float* bs) {
    int grow = 768 + u;
    const float* wr = Wih + grow * 128;
    float s = 0.0f;
    if (k == 0) {
        s = bih[grow];
        for (int m = 0; m < 128; m++) s += bs[m] * wr[m];
    } else if (k == 1) {
        for (int m = 0; m < 128; m++) s += bp[m] * wr[m];
    } else if (k < 5) {
        int d = k - 2;
        for (int m = 0; m < 128; m++) s += Ws[m * 3 + d] * wr[m];
    } else {
        int d = k - 5;
        for (int m = 0; m < 128; m++) s += Wp[m * 3 + d] * wr[m];
    }
    return s;
}

__global__ void prep_kernel(const float* __restrict__ W_ih, const float* __restrict__ b_ih,
                            const float* __restrict__ W_hh, const float* __restrict__ b_hh,
                            const float* __restrict__ Wp,  const float* __restrict__ bp,
                            const float* __restrict__ Ws,  const float* __restrict__ bs,
                            const float* __restrict__ Wd1) {
    int gid = blockIdx.x * blockDim.x + threadIdx.x;
    int nMain = NKB * NMAIN;
    int total = (nMain + 48 + 48 * 8) * 32;
    for (int w = gid; w < total; w += gridDim.x * blockDim.x) {
        int fid = w >> 5, lane = w & 31;
        int tig = lane & 3, g = lane >> 2;
        if (fid < nMain) {
            int kb = fid / NMAIN, rem = fid - kb * NMAIN;
            int ub = rem / 6, n8l = rem - ub * 6;
            int colub = n8l * 8 + g;
            float b0 = bval_main(kb * 8 + tig,     ub, colub, W_ih, b_ih, W_hh, b_hh, Wp, bp, Ws, bs);
            float b1 = bval_main(kb * 8 + tig + 4, ub, colub, W_ih, b_ih, W_hh, b_hh, Wp, bp, Ws, bs);
            g_B2[fid * 32 + lane] = make_float2(to_tf32(b0), to_tf32(b1));
        } else if (fid < nMain + 48) {
            int f = fid - nMain;            // ub*2 + uh
            int ub = f >> 1, n8l = f & 1;
            int u = ub * 16 + n8l * 8 + g;
            float b0 = bval_ni(tig,     u, W_ih, b_ih, Wp, bp, Ws, bs);
            float b1 = bval_ni(tig + 4, u, W_ih, b_ih, Wp, bp, Ws, bs);
            g_Bni[f * 32 + lane] = make_float2(to_tf32(b0), to_tf32(b1));
        } else {
            int f = fid - nMain - 48;       // 48 kb * 8 n8
            int kb = f >> 3, n8 = f & 7;
            int n = n8 * 8 + g;
            int k = kb * 8 + tig;
            float b0 = Wd1[n * HID + k];
            float b1 = Wd1[n * HID + k + 4];
            g_Wd1f2[f * 32 + lane] = make_float2(to_tf32(b0), to_tf32(b1));
        }
    }
}

// -------- main fused GRU rollout: 16 warps = 2 M-halves x 8 col-warps --------
__global__ __launch_bounds__(NTH, 1)
void gru_kernel(const float* __restrict__ init_hidden,
                const float* __restrict__ plan,
                const float* __restrict__ gate,
                const float* __restrict__ init_state,
                const float* __restrict__ bd1,
                const float* __restrict__ Wd2,
                const float* __restrict__ bd2,
                float* __restrict__ out) {
    extern __shared__ float sm[];
    float* sA0   = sm;                  // [MROWS][LDH] ping
    float* sA1   = sA0 + ASZ;           // pong
    float* sDec  = sA1 + ASZ;           // [64][68]
    float* sStat = sDec + 64 * 68;      // [64*3]
    float* sGate = sStat + 192;         // [64]
    float* sbd1  = sGate + 64;          // [64]
    float* sWd2  = sbd1 + 64;           // [3*64]
    float* sbd2  = sWd2 + 192;          // [4]

    const int tid  = threadIdx.x;
    const int warp = tid >> 5;
    const int lane = tid & 31;
    const int g8   = lane >> 2;
    const int tig  = lane & 3;
    const int wsub = warp & 7;          // column-warp within half
    const int mh   = warp >> 3;         // M half (rows mh*32 .. mh*32+31)
    const int row0 = blockIdx.x * MROWS;

    for (int i = tid; i < MROWS * HID; i += NTH) {
        int r = i / HID, u = i - r * HID;
        sA0[r * LDH + 8 + u] = to_tf32(init_hidden[(size_t)row0 * HID + i]);
    }
    if (tid < 192) { sStat[tid] = init_state[(size_t)row0 * 3 + tid]; sWd2[tid] = Wd2[tid]; }
    if (tid < 64)  { sGate[tid] = gate[row0 + tid]; sbd1[tid] = bd1[tid]; }
    if (tid < 3)   sbd2[tid] = bd2[tid];
    __syncthreads();

    for (int t = 0; t < TSTEPS; t++) {
        float* Acur = (t & 1) ? sA1 : sA0;
        float* Anxt = (t & 1) ? sA0 : sA1;

        // ---- phase 0: rowvec = [1, g, S, g*P] into cols 0..7 ----
        if (tid < MROWS * 8) {
            int r = tid >> 3, c = tid & 7;
            float v;
            if (c == 0)      v = 1.0f;
            else if (c == 1) v = sGate[r];
            else if (c < 5)  v = sStat[r * 3 + (c - 2)];
            else             v = sGate[r] * plan[((size_t)(row0 + r) * TSTEPS + t) * 3 + (c - 5)];
            Acur[r * LDH + c] = to_tf32(v);
        }
        __syncthreads();

        // ---- phase 1: GEMM (32 x 1152 dense + n_i micro per half) + gate math ----
        for (int task = 0; task < 3; task++) {
            const int ub = wsub + 8 * task;     // u-block 0..23

            float acc[48];                      // [mf=2][6 frags] x 4  (r,z,n_h)
            float accN[16];                     // [mf=2][uh] x 4       (n_i)
            #pragma unroll
            for (int i = 0; i < 48; i++) acc[i] = 0.0f;
            #pragma unroll
            for (int i = 0; i < 16; i++) accN[i] = 0.0f;

            const float2* Bbase = g_B2 + (size_t)(ub * 6) * 32 + lane;
            float2 bb[2][6];
            #pragma unroll
            for (int j = 0; j < 6; j++) bb[0][j] = Bbase[j * 32];
            float2 bni0 = g_Bni[(ub * 2 + 0) * 32 + lane];
            float2 bni1 = g_Bni[(ub * 2 + 1) * 32 + lane];

            unsigned a[2][8];
            {
                const float* Ab = Acur;
                #pragma unroll
                for (int mf = 0; mf < 2; mf++) {
                    int r0 = mh * 32 + mf * 16 + g8;
                    a[0][mf * 4 + 0] = __float_as_uint(Ab[r0 * LDH + tig]);
                    a[0][mf * 4 + 1] = __float_as_uint(Ab[(r0 + 8) * LDH + tig]);
                    a[0][mf * 4 + 2] = __float_as_uint(Ab[r0 * LDH + tig + 4]);
                    a[0][mf * 4 + 3] = __float_as_uint(Ab[(r0 + 8) * LDH + tig + 4]);
                }
            }

            #pragma unroll 2
            for (int kb = 0; kb < NKB; kb++) {
                const int cur = kb & 1;
                if (kb < NKB - 1) {
                    const float2* Bn = Bbase + (size_t)(kb + 1) * (NMAIN * 32);
                    #pragma unroll
                    for (int j = 0; j < 6; j++) bb[cur ^ 1][j] = Bn[j * 32];
                    const float* Ab = Acur + (kb + 1) * 8;
                    #pragma unroll
                    for (int mf = 0; mf < 2; mf++) {
                        int r0 = mh * 32 + mf * 16 + g8;
                        a[cur ^ 1][mf * 4 + 0] = __float_as_uint(Ab[r0 * LDH + tig]);
                        a[cur ^ 1][mf * 4 + 1] = __float_as_uint(Ab[(r0 + 8) * LDH + tig]);
                        a[cur ^ 1][mf * 4 + 2] = __float_as_uint(Ab[r0 * LDH + tig + 4]);
                        a[cur ^ 1][mf * 4 + 3] = __float_as_uint(Ab[(r0 + 8) * LDH + tig + 4]);
                    }
                }
                if (kb == 0) {   // n_i: rowvec-only contribution
                    unsigned n0x = __float_as_uint(bni0.x), n0y = __float_as_uint(bni0.y);
                    unsigned n1x = __float_as_uint(bni1.x), n1y = __float_as_uint(bni1.y);
                    #pragma unroll
                    for (int mf = 0; mf < 2; mf++) {
                        mma_tf32r(&accN[(mf * 2 + 0) * 4], &a[cur][mf * 4], n0x, n0y);
                        mma_tf32r(&accN[(mf * 2 + 1) * 4], &a[cur][mf * 4], n1x, n1y);
                    }
                }
                #pragma unroll
                for (int f = 0; f < 6; f++) {
                    unsigned b0 = __float_as_uint(bb[cur][f].x);
                    unsigned b1 = __float_as_uint(bb[cur][f].y);
                    #pragma unroll
                    for (int mf = 0; mf < 2; mf++)
                        mma_tf32r(&acc[(mf * 6 + f) * 4], &a[cur][mf * 4], b0, b1);
                }
            }

            // gate math on fragments (f = gate*2 + uh)
            #pragma unroll
            for (int mf = 0; mf < 2; mf++)
            #pragma unroll
            for (int uh = 0; uh < 2; uh++)
            #pragma unroll
            for (int e = 0; e < 4; e++) {
                int row = mh * 32 + mf * 16 + g8 + ((e >> 1) << 3);
                int u   = ub * 16 + uh * 8 + tig * 2 + (e & 1);
                float aR  = acc[(mf * 6 + 0 + uh) * 4 + e];
                float aZ  = acc[(mf * 6 + 2 + uh) * 4 + e];
                float aNh = acc[(mf * 6 + 4 + uh) * 4 + e];
                float aNi = accN[(mf * 2 + uh) * 4 + e];
                float rg = sigf(aR);
                float zg = sigf(aZ);
                float n  = tanhf_fast(aNi + rg * aNh);
                float hold = Acur[row * LDH + 8 + u];
                float hnew = (1.0f - zg) * n + zg * hold;
                Anxt[row * LDH + 8 + u] = to_tf32(hnew);
            }
        }
        // per-half barrier: phase 2 reads only this half's Anxt rows
        asm volatile("bar.sync %0, %1;" :: "r"(1 + mh), "r"(256) : "memory");

        // ---- phase 2: decode layer1 (64x64, K=384), per M-half ----
        {
            float dacc[8];
            #pragma unroll
            for (int i = 0; i < 8; i++) dacc[i] = 0.0f;

            float2 bv = g_Wd1f2[wsub * 32 + lane];
            #pragma unroll 2
            for (int kb = 0; kb < 48; kb++) {
                float2 bcur = bv;
                if (kb < 47) bv = g_Wd1f2[((kb + 1) * 8 + wsub) * 32 + lane];
                unsigned a[8];
                const float* Ab = Anxt + 8 + kb * 8;
                #pragma unroll
                for (int mf = 0; mf < 2; mf++) {
                    int r0 = mh * 32 + mf * 16 + g8;
                    a[mf * 4 + 0] = __float_as_uint(Ab[r0 * LDH + tig]);
                    a[mf * 4 + 1] = __float_as_uint(Ab[(r0 + 8) * LDH + tig]);
                    a[mf * 4 + 2] = __float_as_uint(Ab[r0 * LDH + tig + 4]);
                    a[mf * 4 + 3] = __float_as_uint(Ab[(r0 + 8) * LDH + tig + 4]);
                }
                unsigned b0 = __float_as_uint(bcur.x), b1 = __float_as_uint(bcur.y);
                #pragma unroll
                for (int mf = 0; mf < 2; mf++)
                    mma_tf32r(&dacc[mf * 4], &a[mf * 4], b0, b1);
            }
            #pragma unroll
            for (int mf = 0; mf < 2; mf++)
            #pragma unroll
            for (int e = 0; e < 4; e++) {
                int row = mh * 32 + mf * 16 + g8 + ((e >> 1) << 3);
                int col = wsub * 8 + tig * 2 + (e & 1);
                float v = dacc[mf * 4 + e] + sbd1[col];
                v = v > 0.0f ? v : (__expf(v) - 1.0f);   // ELU
                sDec[row * 68 + col] = v;
            }
        }
        __syncthreads();

        // ---- phase 3: decode layer2 + state update + output ----
        if (tid < 192) {
            int r = tid / 3, c = tid - r * 3;
            float acc = sbd2[c];
            const float* w2 = sWd2 + c * 64;
            const float* dp = sDec + r * 68;
            #pragma unroll 16
            for (int k = 0; k < 64; k++) acc += dp[k] * w2[k];
            float ns = sStat[tid] + acc;
            sStat[tid] = ns;
            out[((size_t)(row0 + r) * TSTEPS + t) * 3 + c] = ns;
        }
        __syncthreads();
    }
}

// -------- launch --------
extern "C" void kernel_launch(void* const* d_in, const int* in_sizes, int n_in,
                              void* d_out, int out_size) {
    const float* init_hidden = (const float*)d_in[0];
    const float* plan        = (const float*)d_in[1];
    const float* gatep       = (const float*)d_in[2];
    const float* init_state  = (const float*)d_in[3];
    const float* Wp   = (const float*)d_in[4];
    const float* bp   = (const float*)d_in[5];
    const float* Ws   = (const float*)d_in[6];
    const float* bs   = (const float*)d_in[7];
    const float* W_ih = (const float*)d_in[8];
    const float* b_ih = (const float*)d_in[9];
    const float* W_hh = (const float*)d_in[10];
    const float* b_hh = (const float*)d_in[11];
    const float* Wd1  = (const float*)d_in[12];
    const float* bd1  = (const float*)d_in[13];
    const float* Wd2  = (const float*)d_in[14];
    const float* bd2  = (const float*)d_in[15];
    float* out = (float*)d_out;

    prep_kernel<<<640, 256>>>(W_ih, b_ih, W_hh, b_hh, Wp, bp, Ws, bs, Wd1);

    const size_t smem_floats = 2 * (size_t)ASZ + 64 * 68 + 192 + 64 + 64 + 192 + 4;
    const size_t smem_bytes = smem_floats * sizeof(float);
    cudaFuncSetAttribute(gru_kernel, cudaFuncAttributeMaxDynamicSharedMemorySize,
                         (int)smem_bytes);

    gru_kernel<<<BATCH / MROWS, NTH, smem_bytes>>>(
        init_hidden, plan, gatep, init_state, bd1, Wd2, bd2, out);
}